// round 15
// baseline (speedup 1.0000x reference)
#include <cuda_runtime.h>

// Problem constants
#define B_  4
#define K_  4
#define D_  96
#define L_  2048
#define N_  16
#define R_  6
#define C_  38          // R + 2N
#define BK_ (B_*K_)     // 16
#define CH  64          // chunks along L
#define LC  (L_/CH)     // 32 steps per chunk
#define DG_ (D_/8)      // 12 d-groups of 8
#define NCH (BK_*3)     // 48 combine chains (bk x g3)

// Scratch (device globals: allocation-free, graph-safe)
// g_dx[((bk*DG + dg)*L + l)*8 + o] = {delta, x} for d = dg*8+o
__device__ __align__(128) float2 g_dx[BK_ * D_ * L_];        // ~25 MB (keep L2-hot)
__device__ __align__(128) float  g_b[BK_ * L_ * N_];         // 2 MB  (keep L2-hot)
__device__ __align__(128) float  g_c[BK_ * L_ * N_];         // 2 MB  (keep L2-hot)
__device__ __align__(128) float2 g_pq[BK_ * D_ * CH * N_];   // {P,q} 12.6 MB
__device__ __align__(128) float  g_h0[BK_ * D_ * CH * N_];   // chunk-entry h 6.3 MB
__device__ int g_cnt[NCH];                                    // combine tickets

// ---- packed f32x2 helpers (FFMA2/FMUL2 are PTX-only) ----
typedef unsigned long long u64;
struct f2 { u64 v; };
__device__ __forceinline__ f2 mk2(float x, float y) {
    f2 r; asm("mov.b64 %0, {%1, %2};" : "=l"(r.v) : "f"(x), "f"(y)); return r;
}
__device__ __forceinline__ void un2(f2 a, float& x, float& y) {
    asm("mov.b64 {%0, %1}, %2;" : "=f"(x), "=f"(y) : "l"(a.v));
}
__device__ __forceinline__ f2 mul2(f2 a, f2 b) {
    f2 r; asm("mul.rn.f32x2 %0, %1, %2;" : "=l"(r.v) : "l"(a.v), "l"(b.v)); return r;
}
__device__ __forceinline__ f2 add2(f2 a, f2 b) {
    f2 r; asm("add.rn.f32x2 %0, %1, %2;" : "=l"(r.v) : "l"(a.v), "l"(b.v)); return r;
}
__device__ __forceinline__ f2 fma2(f2 a, f2 b, f2 c) {
    f2 r; asm("fma.rn.f32x2 %0, %1, %2, %3;" : "=l"(r.v) : "l"(a.v), "l"(b.v), "l"(c.v)); return r;
}
__device__ __forceinline__ float ex2f(float x) {
    float r; asm("ex2.approx.ftz.f32 %0, %1;" : "=f"(r) : "f"(x)); return r;
}
#define LOG2E 1.4426950408889634f

// ---- cp.async helpers ----
__device__ __forceinline__ void cpa16(unsigned saddr, const void* gptr) {
    asm volatile("cp.async.cg.shared.global [%0], [%1], 16;" :: "r"(saddr), "l"(gptr));
}
__device__ __forceinline__ void cpa_commit() { asm volatile("cp.async.commit_group;"); }
__device__ __forceinline__ void cpa_wait1()  { asm volatile("cp.async.wait_group 1;"); }
__device__ __forceinline__ void cpa_wait0()  { asm volatile("cp.async.wait_group 0;"); }

// ---------------------------------------------------------------------------
// Kernel 1: input projection + dt projection + softplus. (R14 form)
// Also resets the 48 combine tickets (k1 completes before k2a starts).
// ---------------------------------------------------------------------------
__global__ __launch_bounds__(256) void k1_proj(
    const float* __restrict__ xs,     // (B,K,D,L)
    const float* __restrict__ Wx,     // (K,C,D)
    const float* __restrict__ Wdt,    // (K,D,R)
    const float* __restrict__ bias)   // (K,D)
{
    __shared__ float sWp[D_][40];
    __shared__ float sWd[D_][8];
    __shared__ float sB[D_];
    __shared__ float sdts[64][8];

    const int tid  = threadIdx.x;
    const int lane = tid & 31;
    const int warp = tid >> 5;
    const int bk   = blockIdx.x >> 5;
    const int k    = bk & (K_ - 1);
    const int lblk = (blockIdx.x & 31) << 6;      // 64 l per block
    const int q4   = lane >> 3;                   // quarter
    const int li   = (warp << 3) | (lane & 7);    // [0,64)
    const int l    = lblk + li;

    if (blockIdx.x == 0 && tid < NCH) g_cnt[tid] = 0;

    for (int i = tid; i < C_ * D_; i += 256) {
        int c = i / D_, d = i - c * D_;
        sWp[d][c] = Wx[k * C_ * D_ + i];
    }
    for (int i = tid; i < D_ * R_; i += 256) {
        int d = i / R_, r = i - d * R_;
        sWd[d][r] = Wdt[k * D_ * R_ + i];
    }
    if (tid < D_) {
        sWp[tid][38] = 0.f; sWp[tid][39] = 0.f;
        sWd[tid][6]  = 0.f; sWd[tid][7]  = 0.f;
        sB[tid] = bias[k * D_ + tid];
    }
    __syncthreads();

    float acc[40];
    #pragma unroll
    for (int c = 0; c < 40; c++) acc[c] = 0.f;

    const float* __restrict__ xp = xs + ((size_t)bk * D_ + q4) * L_ + l;
    #pragma unroll
    for (int dd = 0; dd < 24; dd++) {
        float x = xp[(size_t)(dd * 4) * L_];
        const float4* wr = reinterpret_cast<const float4*>(&sWp[dd * 4 + q4][0]);
        #pragma unroll
        for (int j = 0; j < 10; j++) {
            float4 w = wr[j];
            acc[4*j+0] = fmaf(w.x, x, acc[4*j+0]);
            acc[4*j+1] = fmaf(w.y, x, acc[4*j+1]);
            acc[4*j+2] = fmaf(w.z, x, acc[4*j+2]);
            acc[4*j+3] = fmaf(w.w, x, acc[4*j+3]);
        }
    }
    #pragma unroll
    for (int c = 0; c < C_; c++) {
        acc[c] += __shfl_xor_sync(0xffffffffu, acc[c], 8);
        acc[c] += __shfl_xor_sync(0xffffffffu, acc[c], 16);
    }

    if (q4 == 0) {
        float4* dst = reinterpret_cast<float4*>(g_b) + ((size_t)bk * L_ + l) * 4;
        #pragma unroll
        for (int j = 0; j < 4; j++)
            dst[j] = make_float4(acc[R_+4*j], acc[R_+4*j+1], acc[R_+4*j+2], acc[R_+4*j+3]);
        #pragma unroll
        for (int r = 0; r < R_; r++) sdts[li][r] = acc[r];
    } else if (q4 == 1) {
        float4* dst = reinterpret_cast<float4*>(g_c) + ((size_t)bk * L_ + l) * 4;
        #pragma unroll
        for (int j = 0; j < 4; j++)
            dst[j] = make_float4(acc[R_+N_+4*j], acc[R_+N_+4*j+1],
                                 acc[R_+N_+4*j+2], acc[R_+N_+4*j+3]);
    }
    __syncthreads();

    const int lq = tid >> 3;
    const int o  = tid & 7;
    #pragma unroll
    for (int i = 0; i < 2; i++) {
        const int lt = lq + 32 * i;
        const int l2 = lblk + lt;
        #pragma unroll
        for (int dg = 0; dg < DG_; dg++) {
            const int d = dg * 8 + o;
            float t = sB[d];
            #pragma unroll
            for (int r = 0; r < R_; r++) t = fmaf(sWd[d][r], sdts[lt][r], t);
            float sp = (t > 15.f) ? t : __logf(1.f + __expf(t));
            float x  = xs[((size_t)bk * D_ + d) * L_ + l2];
            g_dx[(((size_t)bk * DG_ + dg) * L_ + l2) * 8 + o] = make_float2(sp, x);
        }
    }
}

// ---------------------------------------------------------------------------
// Pass A: per-chunk local scan q (h0=0) and decay P = exp2(A2 * sum(delta)).
// Split-group cp.async: group1 = steps 0-15, group2 = steps 16-31, both
// issued up front; compute starts after group1 (wait_group 1).
// Last block per (bk,g3) chain runs the h0 combine inline (replaces k2b).
// ---------------------------------------------------------------------------
__global__ __launch_bounds__(128, 12) void k2a_chunk(
    const float* __restrict__ Alogs)  // (K*D, N)
{
    __shared__ __align__(16) float4 s_dx4[512];
    __shared__ __align__(16) float  s_b[LC * N_];
    __shared__ int s_ticket;

    const int tid  = threadIdx.x;
    const int lane = tid & 31;
    const int warp = tid >> 5;
    const int o    = lane >> 2;
    const int jj   = lane & 3;
    const int g3   = blockIdx.x % 3;
    const int c    = (blockIdx.x / 3) & (CH - 1);
    const int bk   = blockIdx.x / (3 * CH);
    const int dg   = g3 * 4 + warp;
    const int d    = dg * 8 + o;
    const int k    = bk & (K_ - 1);
    const int kd   = k * D_ + d;
    const int n0   = jj * 4;
    const int l0   = c * LC;
    const int chain = bk * 3 + g3;

    const unsigned sdb = (unsigned)__cvta_generic_to_shared(s_dx4);
    const unsigned sbb = (unsigned)__cvta_generic_to_shared(s_b);

    const int w2 = tid >> 5;                  // producer dg region
    const int r2 = (tid & 31) * 2;
    const float4* dxb = reinterpret_cast<const float4*>(g_dx)
                        + (((size_t)bk * DG_ + g3 * 4 + w2) * L_ + l0) * 4;
    const float4* bsrc = reinterpret_cast<const float4*>(g_b)
                         + ((size_t)bk * L_ + l0) * 4;

    // group 1: steps 0-15
    cpa16(sdb + (unsigned)((w2 * 128 + r2) * 16),     dxb + r2);
    cpa16(sdb + (unsigned)((w2 * 128 + r2 + 1) * 16), dxb + r2 + 1);
    if (tid < 64) cpa16(sbb + (unsigned)(tid * 16), bsrc + tid);
    cpa_commit();
    // group 2: steps 16-31
    cpa16(sdb + (unsigned)((w2 * 128 + 64 + r2) * 16),     dxb + 64 + r2);
    cpa16(sdb + (unsigned)((w2 * 128 + 64 + r2 + 1) * 16), dxb + 64 + r2 + 1);
    if (tid < 64) cpa16(sbb + (unsigned)((64 + tid) * 16), bsrc + 64 + tid);
    cpa_commit();

    float4 al = *reinterpret_cast<const float4*>(&Alogs[kd * N_ + n0]);
    const float a0 = -__expf(al.x) * LOG2E;
    const float a1 = -__expf(al.y) * LOG2E;
    const float a2 = -__expf(al.z) * LOG2E;
    const float a3 = -__expf(al.w) * LOG2E;
    const f2 a01 = mk2(a0, a1);
    const f2 a23 = mk2(a2, a3);

    const float2* __restrict__ sdx = reinterpret_cast<const float2*>(s_dx4);
    f2 h01 = mk2(0.f, 0.f), h23 = mk2(0.f, 0.f);
    float dsum = 0.f;

    cpa_wait1();
    __syncthreads();
    #pragma unroll
    for (int ph = 0; ph < 2; ph++) {
        #pragma unroll 8
        for (int t2 = 0; t2 < 16; t2++) {
            const int tt = ph * 16 + t2;
            float4 b4 = *reinterpret_cast<const float4*>(&s_b[tt * N_ + n0]);
            float2 dx = sdx[(warp * LC + tt) * 8 + o];

            f2 dd = mk2(dx.x, dx.x);
            float e0, e1, e2, e3;
            un2(mul2(dd, a01), e0, e1);
            un2(mul2(dd, a23), e2, e3);
            f2 dA01 = mk2(ex2f(e0), ex2f(e1));
            f2 dA23 = mk2(ex2f(e2), ex2f(e3));

            float dxu = dx.x * dx.y;
            f2 du = mk2(dxu, dxu);
            h01 = fma2(dA01, h01, mul2(du, mk2(b4.x, b4.y)));
            h23 = fma2(dA23, h23, mul2(du, mk2(b4.z, b4.w)));
            dsum += dx.x;
        }
        if (ph == 0) { cpa_wait0(); __syncthreads(); }
    }

    float q0, q1, q2, q3;
    un2(h01, q0, q1); un2(h23, q2, q3);
    float4* dst = reinterpret_cast<float4*>(g_pq)
                  + ((((size_t)bk * D_ + d) * CH + c) * N_ + n0) / 2;
    dst[0] = make_float4(ex2f(a0 * dsum), q0, ex2f(a1 * dsum), q1);
    dst[1] = make_float4(ex2f(a2 * dsum), q2, ex2f(a3 * dsum), q3);

    // ---- last-block combine (replaces k2b) ----
    __threadfence();
    __syncthreads();
    if (tid == 0) s_ticket = atomicAdd(&g_cnt[chain], 1);
    __syncthreads();
    if (s_ticket == CH - 1) {
        // this chain covers d in [g3*32, g3*32+32), all 16 n
        size_t base[4];
        float h[4];
        #pragma unroll
        for (int j = 0; j < 4; j++) {
            int cid = j * 128 + tid;
            int dl = cid >> 4, n = cid & 15;
            base[j] = (((size_t)bk * D_ + g3 * 32 + dl) * CH) * N_ + n;
            h[j] = 0.f;
        }
        #pragma unroll 4
        for (int c2 = 0; c2 < CH; c2++) {
            #pragma unroll
            for (int j = 0; j < 4; j++) {
                const size_t idx = base[j] + (size_t)c2 * N_;
                g_h0[idx] = h[j];
                float2 pq = __ldcg(&g_pq[idx]);
                h[j] = fmaf(pq.x, h[j], pq.y);
            }
        }
    }
}

// ---------------------------------------------------------------------------
// Pass C: re-scan from known entry state. Split-group cp.async (steps 0-15 /
// 16-31); 2-SHFL quad butterfly; STG.128 per 16-step window.
// h0 read via __ldcs; y written via __stcs (never re-read).
// ---------------------------------------------------------------------------
__global__ __launch_bounds__(128, 12) void k2c_scan(
    const float* __restrict__ Alogs,  // (K*D, N)
    const float* __restrict__ Ds,     // (K*D)
    float* __restrict__ out)          // (B,K,D,L)
{
    __shared__ __align__(16) float4 s_dx4[512];
    __shared__ __align__(16) float  s_b[LC * N_];
    __shared__ __align__(16) float  s_c[LC * N_];

    const int tid  = threadIdx.x;
    const int lane = tid & 31;
    const int warp = tid >> 5;
    const int o    = lane >> 2;
    const int jj   = lane & 3;
    const int g3   = blockIdx.x % 3;
    const int c    = (blockIdx.x / 3) & (CH - 1);
    const int bk   = blockIdx.x / (3 * CH);
    const int dg   = g3 * 4 + warp;
    const int d    = dg * 8 + o;
    const int k    = bk & (K_ - 1);
    const int kd   = k * D_ + d;
    const int n0   = jj * 4;
    const int l0   = c * LC;

    const unsigned sdb = (unsigned)__cvta_generic_to_shared(s_dx4);
    const unsigned sbb = (unsigned)__cvta_generic_to_shared(s_b);
    const unsigned scb = (unsigned)__cvta_generic_to_shared(s_c);

    const int w2 = tid >> 5;
    const int r2 = (tid & 31) * 2;
    const float4* dxb = reinterpret_cast<const float4*>(g_dx)
                        + (((size_t)bk * DG_ + g3 * 4 + w2) * L_ + l0) * 4;
    const float4* bsrc = reinterpret_cast<const float4*>(g_b)
                         + ((size_t)bk * L_ + l0) * 4;
    const float4* csrc = reinterpret_cast<const float4*>(g_c)
                         + ((size_t)bk * L_ + l0) * 4;

    // group 1: steps 0-15
    cpa16(sdb + (unsigned)((w2 * 128 + r2) * 16),     dxb + r2);
    cpa16(sdb + (unsigned)((w2 * 128 + r2 + 1) * 16), dxb + r2 + 1);
    if (tid < 64) cpa16(sbb + (unsigned)(tid * 16), bsrc + tid);
    else          cpa16(scb + (unsigned)((tid - 64) * 16), csrc + (tid - 64));
    cpa_commit();
    // group 2: steps 16-31
    cpa16(sdb + (unsigned)((w2 * 128 + 64 + r2) * 16),     dxb + 64 + r2);
    cpa16(sdb + (unsigned)((w2 * 128 + 64 + r2 + 1) * 16), dxb + 64 + r2 + 1);
    if (tid < 64) cpa16(sbb + (unsigned)((64 + tid) * 16), bsrc + 64 + tid);
    else          cpa16(scb + (unsigned)((64 + tid - 64) * 16), csrc + 64 + tid - 64);
    cpa_commit();

    float4 al = *reinterpret_cast<const float4*>(&Alogs[kd * N_ + n0]);
    const f2 a01 = mk2(-__expf(al.x) * LOG2E, -__expf(al.y) * LOG2E);
    const f2 a23 = mk2(-__expf(al.z) * LOG2E, -__expf(al.w) * LOG2E);
    const float Dd = Ds[kd];
    float4 h0v = __ldcs(reinterpret_cast<const float4*>(
        &g_h0[(((size_t)bk * D_ + d) * CH + c) * N_ + n0]));

    const float2* __restrict__ sdx = reinterpret_cast<const float2*>(s_dx4);
    f2 h01 = mk2(h0v.x, h0v.y), h23 = mk2(h0v.z, h0v.w);
    float* __restrict__ yp = out + ((size_t)bk * D_ + d) * L_ + l0;

    cpa_wait1();
    __syncthreads();
    #pragma unroll
    for (int tw = 0; tw < 2; tw++) {
        float y0 = 0.f, y1 = 0.f, y2 = 0.f, y3 = 0.f;
        #pragma unroll
        for (int t2 = 0; t2 < 16; t2++) {
            const int tt = tw * 16 + t2;
            float4 b4 = *reinterpret_cast<const float4*>(&s_b[tt * N_ + n0]);
            float4 c4 = *reinterpret_cast<const float4*>(&s_c[tt * N_ + n0]);
            float2 dx = sdx[(warp * LC + tt) * 8 + o];

            f2 dd = mk2(dx.x, dx.x);
            float e0, e1, e2, e3;
            un2(mul2(dd, a01), e0, e1);
            un2(mul2(dd, a23), e2, e3);
            f2 dA01 = mk2(ex2f(e0), ex2f(e1));
            f2 dA23 = mk2(ex2f(e2), ex2f(e3));

            float dxu = dx.x * dx.y;
            f2 du = mk2(dxu, dxu);
            h01 = fma2(dA01, h01, mul2(du, mk2(b4.x, b4.y)));
            h23 = fma2(dA23, h23, mul2(du, mk2(b4.z, b4.w)));

            f2 ps2 = add2(mul2(h01, mk2(c4.x, c4.y)), mul2(h23, mk2(c4.z, c4.w)));
            float pa, pb; un2(ps2, pa, pb);
            float p = pa + pb;
            p += __shfl_xor_sync(0xffffffffu, p, 1);
            p += __shfl_xor_sync(0xffffffffu, p, 2);
            float ysum = fmaf(Dd, dx.y, p);

            if (jj == (t2 >> 2)) {
                if      ((t2 & 3) == 0) y0 = ysum;
                else if ((t2 & 3) == 1) y1 = ysum;
                else if ((t2 & 3) == 2) y2 = ysum;
                else                    y3 = ysum;
            }
        }
        __stcs(reinterpret_cast<float4*>(yp + tw * 16 + jj * 4),
               make_float4(y0, y1, y2, y3));
        if (tw == 0) { cpa_wait0(); __syncthreads(); }
    }
}

// ---------------------------------------------------------------------------
extern "C" void kernel_launch(void* const* d_in, const int* in_sizes, int n_in,
                              void* d_out, int out_size)
{
    const float* xs    = (const float*)d_in[0];   // (B,K,D,L)
    const float* Alogs = (const float*)d_in[1];   // (K*D, N)
    const float* Ds    = (const float*)d_in[2];   // (K*D)
    const float* Wdt   = (const float*)d_in[3];   // (K,D,R)
    const float* bias  = (const float*)d_in[4];   // (K,D)
    const float* Wx    = (const float*)d_in[5];   // (K,C,D)
    float* out = (float*)d_out;

    k1_proj<<<BK_ * 32, 256>>>(xs, Wx, Wdt, bias);             // 512 blocks
    k2a_chunk<<<BK_ * CH * 3, 128>>>(Alogs);                   // 3072 blocks (+combine)
    k2c_scan<<<BK_ * CH * 3, 128>>>(Alogs, Ds, out);           // 3072 blocks
}

// round 16
// speedup vs baseline: 1.5664x; 1.5664x over previous
#include <cuda_runtime.h>

// Problem constants
#define B_  4
#define K_  4
#define D_  96
#define L_  2048
#define N_  16
#define R_  6
#define C_  38          // R + 2N
#define BK_ (B_*K_)     // 16
#define CH  64          // chunks along L
#define LC  (L_/CH)     // 32 steps per chunk
#define DG_ (D_/8)      // 12 d-groups of 8

// Scratch (device globals: allocation-free, graph-safe)
// g_dx[((bk*DG + dg)*L + l)*8 + o] = {delta, x} for d = dg*8+o
__device__ __align__(128) float2 g_dx[BK_ * D_ * L_];        // ~25 MB (keep L2-hot)
__device__ __align__(128) float  g_b[BK_ * L_ * N_];         // 2 MB  (keep L2-hot)
__device__ __align__(128) float  g_c[BK_ * L_ * N_];         // 2 MB  (keep L2-hot)
__device__ __align__(128) float2 g_pq[BK_ * D_ * CH * N_];   // {P,q} 12.6 MB (streamed)
__device__ __align__(128) float  g_h0[BK_ * D_ * CH * N_];   // chunk-entry h 6.3 MB

// ---- packed f32x2 helpers (FFMA2/FMUL2 are PTX-only) ----
typedef unsigned long long u64;
struct f2 { u64 v; };
__device__ __forceinline__ f2 mk2(float x, float y) {
    f2 r; asm("mov.b64 %0, {%1, %2};" : "=l"(r.v) : "f"(x), "f"(y)); return r;
}
__device__ __forceinline__ void un2(f2 a, float& x, float& y) {
    asm("mov.b64 {%0, %1}, %2;" : "=f"(x), "=f"(y) : "l"(a.v));
}
__device__ __forceinline__ f2 mul2(f2 a, f2 b) {
    f2 r; asm("mul.rn.f32x2 %0, %1, %2;" : "=l"(r.v) : "l"(a.v), "l"(b.v)); return r;
}
__device__ __forceinline__ f2 add2(f2 a, f2 b) {
    f2 r; asm("add.rn.f32x2 %0, %1, %2;" : "=l"(r.v) : "l"(a.v), "l"(b.v)); return r;
}
__device__ __forceinline__ f2 fma2(f2 a, f2 b, f2 c) {
    f2 r; asm("fma.rn.f32x2 %0, %1, %2, %3;" : "=l"(r.v) : "l"(a.v), "l"(b.v), "l"(c.v)); return r;
}
__device__ __forceinline__ float ex2f(float x) {
    float r; asm("ex2.approx.ftz.f32 %0, %1;" : "=f"(r) : "f"(x)); return r;
}
#define LOG2E 1.4426950408889634f

// ---- cp.async helpers ----
__device__ __forceinline__ void cpa16(unsigned saddr, const void* gptr) {
    asm volatile("cp.async.cg.shared.global [%0], [%1], 16;" :: "r"(saddr), "l"(gptr));
}
__device__ __forceinline__ void cpa_commit() { asm volatile("cp.async.commit_group;"); }
__device__ __forceinline__ void cpa_wait0()  { asm volatile("cp.async.wait_group 0;"); }

// ---------------------------------------------------------------------------
// Kernel 1: input projection + dt projection + softplus.
// TWO-PASS channel split: 20 of 40 channels per pass -> acc regs halve,
// __launch_bounds__(256,3) -> 3 blocks/SM. Combined channels staged in sAcc.
// ---------------------------------------------------------------------------
__global__ __launch_bounds__(256, 3) void k1_proj(
    const float* __restrict__ xs,     // (B,K,D,L)
    const float* __restrict__ Wx,     // (K,C,D)
    const float* __restrict__ Wdt,    // (K,D,R)
    const float* __restrict__ bias)   // (K,D)
{
    __shared__ float sWp[D_][40];     // 15.4 KB
    __shared__ float sWd[D_][8];      //  3.1 KB
    __shared__ float sB[D_];          //  0.4 KB
    __shared__ float sAcc[64][40];    // 10.2 KB combined channels per l

    const int tid  = threadIdx.x;
    const int lane = tid & 31;
    const int warp = tid >> 5;
    const int bk   = blockIdx.x >> 5;
    const int k    = bk & (K_ - 1);
    const int lblk = (blockIdx.x & 31) << 6;      // 64 l per block
    const int q4   = lane >> 3;                   // quarter
    const int li   = (warp << 3) | (lane & 7);    // [0,64)
    const int l    = lblk + li;

    for (int i = tid; i < C_ * D_; i += 256) {
        int c = i / D_, d = i - c * D_;
        sWp[d][c] = Wx[k * C_ * D_ + i];
    }
    for (int i = tid; i < D_ * R_; i += 256) {
        int d = i / R_, r = i - d * R_;
        sWd[d][r] = Wdt[k * D_ * R_ + i];
    }
    if (tid < D_) {
        sWp[tid][38] = 0.f; sWp[tid][39] = 0.f;
        sWd[tid][6]  = 0.f; sWd[tid][7]  = 0.f;
        sB[tid] = bias[k * D_ + tid];
    }
    __syncthreads();

    const float* __restrict__ xp = xs + ((size_t)bk * D_ + q4) * L_ + l;

    // Two passes over d, 20 channels each
    #pragma unroll
    for (int p = 0; p < 2; p++) {
        float acc[20];
        #pragma unroll
        for (int c = 0; c < 20; c++) acc[c] = 0.f;

        #pragma unroll
        for (int dd = 0; dd < 24; dd++) {
            float x = xp[(size_t)(dd * 4) * L_];              // pass 2: L1 hit
            const float4* wr = reinterpret_cast<const float4*>(
                &sWp[dd * 4 + q4][p * 20]);
            #pragma unroll
            for (int j = 0; j < 5; j++) {
                float4 w = wr[j];
                acc[4*j+0] = fmaf(w.x, x, acc[4*j+0]);
                acc[4*j+1] = fmaf(w.y, x, acc[4*j+1]);
                acc[4*j+2] = fmaf(w.z, x, acc[4*j+2]);
                acc[4*j+3] = fmaf(w.w, x, acc[4*j+3]);
            }
        }
        // combine the four quarters (lanes li, li+8, li+16, li+24)
        #pragma unroll
        for (int c = 0; c < 20; c++) {
            acc[c] += __shfl_xor_sync(0xffffffffu, acc[c], 8);
            acc[c] += __shfl_xor_sync(0xffffffffu, acc[c], 16);
        }
        if (q4 == 0) {
            #pragma unroll
            for (int c = 0; c < 20; c++) sAcc[li][p * 20 + c] = acc[c];
        }
    }
    __syncthreads();

    // Write g_b / g_c from sAcc: thread i -> (l = i>>2, j = i&3)
    {
        const int lq2 = tid >> 2;
        const int j   = tid & 3;
        const int lg  = lblk + lq2;
        float4 vb = make_float4(sAcc[lq2][R_ + 4*j],     sAcc[lq2][R_ + 4*j + 1],
                                sAcc[lq2][R_ + 4*j + 2], sAcc[lq2][R_ + 4*j + 3]);
        reinterpret_cast<float4*>(g_b)[((size_t)bk * L_ + lg) * 4 + j] = vb;
        float4 vc = make_float4(sAcc[lq2][R_+N_ + 4*j],     sAcc[lq2][R_+N_ + 4*j + 1],
                                sAcc[lq2][R_+N_ + 4*j + 2], sAcc[lq2][R_+N_ + 4*j + 3]);
        reinterpret_cast<float4*>(g_c)[((size_t)bk * L_ + lg) * 4 + j] = vc;
    }
    __syncthreads();

    // Phase 2: thread = (lq = tid>>3 in [0,32), o = tid&7); 2 x 32 l halves
    const int lq = tid >> 3;
    const int o  = tid & 7;
    #pragma unroll
    for (int i = 0; i < 2; i++) {
        const int lt = lq + 32 * i;
        const int l2 = lblk + lt;
        #pragma unroll
        for (int dg = 0; dg < DG_; dg++) {
            const int d = dg * 8 + o;
            float t = sB[d];
            #pragma unroll
            for (int r = 0; r < R_; r++) t = fmaf(sWd[d][r], sAcc[lt][r], t);
            float sp = (t > 15.f) ? t : __logf(1.f + __expf(t));
            float x  = xs[((size_t)bk * D_ + d) * L_ + l2];
            g_dx[(((size_t)bk * DG_ + dg) * L_ + l2) * 8 + o] = make_float2(sp, x);
        }
    }
}

// ---------------------------------------------------------------------------
// Pass A: per-chunk local scan q (h0=0) and decay P = exp2(A2 * sum(delta)).
// Single-shot cp.async (dx 8KB + B 2KB), one barrier, 32 straight steps.
// g_pq written with evict-first (__stcs). (R14 form, unchanged)
// ---------------------------------------------------------------------------
__global__ __launch_bounds__(128, 12) void k2a_chunk(
    const float* __restrict__ Alogs)  // (K*D, N)
{
    __shared__ __align__(16) float4 s_dx4[512];
    __shared__ __align__(16) float  s_b[LC * N_];

    const int tid  = threadIdx.x;
    const int lane = tid & 31;
    const int warp = tid >> 5;
    const int o    = lane >> 2;
    const int jj   = lane & 3;
    const int g3   = blockIdx.x % 3;
    const int c    = (blockIdx.x / 3) & (CH - 1);
    const int bk   = blockIdx.x / (3 * CH);
    const int dg   = g3 * 4 + warp;
    const int d    = dg * 8 + o;
    const int k    = bk & (K_ - 1);
    const int kd   = k * D_ + d;
    const int n0   = jj * 4;
    const int l0   = c * LC;

    const unsigned sdb = (unsigned)__cvta_generic_to_shared(s_dx4);
    const unsigned sbb = (unsigned)__cvta_generic_to_shared(s_b);
    const float4* dxsrc = reinterpret_cast<const float4*>(g_dx);

    #pragma unroll
    for (int j = 0; j < 4; j++) {
        int i = tid + j * 128, w = i >> 7, r = i & 127;
        cpa16(sdb + (unsigned)(i * 16),
              dxsrc + (((size_t)bk * DG_ + g3 * 4 + w) * L_ + l0) * 4 + r);
    }
    cpa16(sbb + (unsigned)(tid * 16),
          reinterpret_cast<const float4*>(g_b + ((size_t)bk * L_ + l0) * 16) + tid);
    cpa_commit();

    float4 al = *reinterpret_cast<const float4*>(&Alogs[kd * N_ + n0]);
    const float a0 = -__expf(al.x) * LOG2E;
    const float a1 = -__expf(al.y) * LOG2E;
    const float a2 = -__expf(al.z) * LOG2E;
    const float a3 = -__expf(al.w) * LOG2E;
    const f2 a01 = mk2(a0, a1);
    const f2 a23 = mk2(a2, a3);

    cpa_wait0();
    __syncthreads();

    const float2* __restrict__ sdx = reinterpret_cast<const float2*>(s_dx4);
    f2 h01 = mk2(0.f, 0.f), h23 = mk2(0.f, 0.f);
    float dsum = 0.f;

    #pragma unroll 8
    for (int tt = 0; tt < LC; tt++) {
        float4 b4 = *reinterpret_cast<const float4*>(&s_b[tt * N_ + n0]);
        float2 dx = sdx[(warp * LC + tt) * 8 + o];

        f2 dd = mk2(dx.x, dx.x);
        float e0, e1, e2, e3;
        un2(mul2(dd, a01), e0, e1);
        un2(mul2(dd, a23), e2, e3);
        f2 dA01 = mk2(ex2f(e0), ex2f(e1));
        f2 dA23 = mk2(ex2f(e2), ex2f(e3));

        float dxu = dx.x * dx.y;
        f2 du = mk2(dxu, dxu);
        h01 = fma2(dA01, h01, mul2(du, mk2(b4.x, b4.y)));
        h23 = fma2(dA23, h23, mul2(du, mk2(b4.z, b4.w)));
        dsum += dx.x;
    }

    float q0, q1, q2, q3;
    un2(h01, q0, q1); un2(h23, q2, q3);
    float4* dst = reinterpret_cast<float4*>(g_pq)
                  + ((((size_t)bk * D_ + d) * CH + c) * N_ + n0) / 2;
    __stcs(dst,     make_float4(ex2f(a0 * dsum), q0, ex2f(a1 * dsum), q1));
    __stcs(dst + 1, make_float4(ex2f(a2 * dsum), q2, ex2f(a3 * dsum), q3));
}

// ---------------------------------------------------------------------------
// Pass B: block per (bkd). Streaming (__ldcs) 8KB load to smem, 16-lane
// serial scan, coalesced h0 store. (R14 form, unchanged)
// ---------------------------------------------------------------------------
__global__ __launch_bounds__(128) void k2b_combine()
{
    __shared__ float2 s_pq[CH * N_];
    __shared__ float  s_h0[CH * N_];

    const int tid = threadIdx.x;
    const size_t base = (size_t)blockIdx.x * CH * N_;

    #pragma unroll
    for (int i = tid; i < CH * N_; i += 128) s_pq[i] = __ldcs(&g_pq[base + i]);
    __syncthreads();

    if (tid < N_) {
        float h = 0.f;
        #pragma unroll 8
        for (int c2 = 0; c2 < CH; c2++) {
            s_h0[c2 * N_ + tid] = h;
            float2 pq = s_pq[c2 * N_ + tid];
            h = fmaf(pq.x, h, pq.y);
        }
    }
    __syncthreads();

    #pragma unroll
    for (int i = tid; i < CH * N_; i += 128) g_h0[base + i] = s_h0[i];
}

// ---------------------------------------------------------------------------
// Pass C: re-scan from known entry state. Single-shot cp.async (dx+B+C),
// one barrier, 32 steps; 2-SHFL quad butterfly; STG.128 per 16-step window.
// (R14 form, unchanged)
// ---------------------------------------------------------------------------
__global__ __launch_bounds__(128, 12) void k2c_scan(
    const float* __restrict__ Alogs,  // (K*D, N)
    const float* __restrict__ Ds,     // (K*D)
    float* __restrict__ out)          // (B,K,D,L)
{
    __shared__ __align__(16) float4 s_dx4[512];
    __shared__ __align__(16) float  s_b[LC * N_];
    __shared__ __align__(16) float  s_c[LC * N_];

    const int tid  = threadIdx.x;
    const int lane = tid & 31;
    const int warp = tid >> 5;
    const int o    = lane >> 2;
    const int jj   = lane & 3;
    const int g3   = blockIdx.x % 3;
    const int c    = (blockIdx.x / 3) & (CH - 1);
    const int bk   = blockIdx.x / (3 * CH);
    const int dg   = g3 * 4 + warp;
    const int d    = dg * 8 + o;
    const int k    = bk & (K_ - 1);
    const int kd   = k * D_ + d;
    const int n0   = jj * 4;
    const int l0   = c * LC;

    const unsigned sdb = (unsigned)__cvta_generic_to_shared(s_dx4);
    const unsigned sbb = (unsigned)__cvta_generic_to_shared(s_b);
    const unsigned scb = (unsigned)__cvta_generic_to_shared(s_c);
    const float4* dxsrc = reinterpret_cast<const float4*>(g_dx);

    #pragma unroll
    for (int j = 0; j < 4; j++) {
        int i = tid + j * 128, w = i >> 7, r = i & 127;
        cpa16(sdb + (unsigned)(i * 16),
              dxsrc + (((size_t)bk * DG_ + g3 * 4 + w) * L_ + l0) * 4 + r);
    }
    cpa16(sbb + (unsigned)(tid * 16),
          reinterpret_cast<const float4*>(g_b + ((size_t)bk * L_ + l0) * 16) + tid);
    cpa16(scb + (unsigned)(tid * 16),
          reinterpret_cast<const float4*>(g_c + ((size_t)bk * L_ + l0) * 16) + tid);
    cpa_commit();

    float4 al = *reinterpret_cast<const float4*>(&Alogs[kd * N_ + n0]);
    const f2 a01 = mk2(-__expf(al.x) * LOG2E, -__expf(al.y) * LOG2E);
    const f2 a23 = mk2(-__expf(al.z) * LOG2E, -__expf(al.w) * LOG2E);
    const float Dd = Ds[kd];
    float4 h0v = __ldcs(reinterpret_cast<const float4*>(
        &g_h0[(((size_t)bk * D_ + d) * CH + c) * N_ + n0]));

    cpa_wait0();
    __syncthreads();

    const float2* __restrict__ sdx = reinterpret_cast<const float2*>(s_dx4);
    f2 h01 = mk2(h0v.x, h0v.y), h23 = mk2(h0v.z, h0v.w);
    float* __restrict__ yp = out + ((size_t)bk * D_ + d) * L_ + l0;

    #pragma unroll
    for (int tw = 0; tw < 2; tw++) {
        float y0 = 0.f, y1 = 0.f, y2 = 0.f, y3 = 0.f;
        #pragma unroll
        for (int t2 = 0; t2 < 16; t2++) {
            const int tt = tw * 16 + t2;
            float4 b4 = *reinterpret_cast<const float4*>(&s_b[tt * N_ + n0]);
            float4 c4 = *reinterpret_cast<const float4*>(&s_c[tt * N_ + n0]);
            float2 dx = sdx[(warp * LC + tt) * 8 + o];

            f2 dd = mk2(dx.x, dx.x);
            float e0, e1, e2, e3;
            un2(mul2(dd, a01), e0, e1);
            un2(mul2(dd, a23), e2, e3);
            f2 dA01 = mk2(ex2f(e0), ex2f(e1));
            f2 dA23 = mk2(ex2f(e2), ex2f(e3));

            float dxu = dx.x * dx.y;
            f2 du = mk2(dxu, dxu);
            h01 = fma2(dA01, h01, mul2(du, mk2(b4.x, b4.y)));
            h23 = fma2(dA23, h23, mul2(du, mk2(b4.z, b4.w)));

            f2 ps2 = add2(mul2(h01, mk2(c4.x, c4.y)), mul2(h23, mk2(c4.z, c4.w)));
            float pa, pb; un2(ps2, pa, pb);
            float p = pa + pb;
            p += __shfl_xor_sync(0xffffffffu, p, 1);
            p += __shfl_xor_sync(0xffffffffu, p, 2);
            float ysum = fmaf(Dd, dx.y, p);

            if (jj == (t2 >> 2)) {
                if      ((t2 & 3) == 0) y0 = ysum;
                else if ((t2 & 3) == 1) y1 = ysum;
                else if ((t2 & 3) == 2) y2 = ysum;
                else                    y3 = ysum;
            }
        }
        __stcs(reinterpret_cast<float4*>(yp + tw * 16 + jj * 4),
               make_float4(y0, y1, y2, y3));
    }
}

// ---------------------------------------------------------------------------
extern "C" void kernel_launch(void* const* d_in, const int* in_sizes, int n_in,
                              void* d_out, int out_size)
{
    const float* xs    = (const float*)d_in[0];   // (B,K,D,L)
    const float* Alogs = (const float*)d_in[1];   // (K*D, N)
    const float* Ds    = (const float*)d_in[2];   // (K*D)
    const float* Wdt   = (const float*)d_in[3];   // (K,D,R)
    const float* bias  = (const float*)d_in[4];   // (K,D)
    const float* Wx    = (const float*)d_in[5];   // (K,C,D)
    float* out = (float*)d_out;

    k1_proj<<<BK_ * 32, 256>>>(xs, Wx, Wdt, bias);             // 512 blocks
    k2a_chunk<<<BK_ * CH * 3, 128>>>(Alogs);                   // 3072 blocks
    k2b_combine<<<BK_ * D_, 128>>>();                          // 1536 blocks
    k2c_scan<<<BK_ * CH * 3, 128>>>(Alogs, Ds, out);           // 3072 blocks
}